// round 5
// baseline (speedup 1.0000x reference)
#include <cuda_runtime.h>
#include <cuda_bf16.h>

// ConditionalCNF: B=524288 samples, scalar z, cond dim 8, 3-layer tanh MLP H=32,
// RK4 N_STEPS=20 over [0,1], augmented with exact divergence.
//
// Strategy: one thread per sample. Weights broadcast from shared memory.
// cond-dependent layer-1 preactivation hoisted out of the 80 evals.
// The two 32x32 matvecs per eval (h-path and d-path share W2 rows) are done
// with fma.rn.f32x2 packed over K-pairs: weights load pre-packed from shared.

static constexpr int H = 32;
static constexpr int C = 8;
static constexpr int DIN = 9;          // 1 + C
static constexpr int NSTEPS = 20;

__device__ __forceinline__ float tanh_fast(float x) {
    // tanh(x) = 1 - 2/(exp(2x)+1), via ex2.approx (2 ulp) + rcp.approx (1 ulp).
    // Saturates correctly at +/-inf. Rel err ~1e-6 << 1e-3 tolerance.
    float e;
    asm("ex2.approx.f32 %0, %1;" : "=f"(e) : "f"(x * 2.8853900817779268f));
    float r;
    asm("rcp.approx.f32 %0, %1;" : "=f"(r) : "f"(e + 1.0f));
    return fmaf(-2.0f, r, 1.0f);
}

__device__ __forceinline__ void fma2(unsigned long long& d,
                                     unsigned long long a,
                                     unsigned long long b) {
    asm("fma.rn.f32x2 %0, %1, %2, %3;" : "=l"(d) : "l"(a), "l"(b), "l"(d));
}

__device__ __forceinline__ unsigned long long pack2(float lo, float hi) {
    unsigned long long r;
    asm("mov.b64 %0, {%1, %2};" : "=l"(r) : "f"(lo), "f"(hi));
    return r;
}

__device__ __forceinline__ void unpack2(unsigned long long v, float& lo, float& hi) {
    asm("mov.b64 {%0, %1}, %2;" : "=f"(lo), "=f"(hi) : "l"(v));
}

__global__ void __launch_bounds__(128)
cnf_kernel(const float* __restrict__ T,
           const float* __restrict__ cond,
           const float* __restrict__ gW1,
           const float* __restrict__ gb1,
           const float* __restrict__ gW2,
           const float* __restrict__ gb2,
           const float* __restrict__ gW3,
           const float* __restrict__ gb3,
           float* __restrict__ out,
           int B)
{
    __shared__ __align__(16) float sW2[H * H];   // row-major, pairs contiguous
    __shared__ float sb2[H];
    __shared__ float sW3[H];
    __shared__ float sw10[H];                    // W1[:,0]
    __shared__ float sW1c[H * C];                // W1[:,1:9] row-major [j][c]
    __shared__ float sb1[H];

    const int tid = threadIdx.x;
    for (int i = tid; i < H * H; i += blockDim.x) sW2[i] = gW2[i];
    if (tid < H) {
        sb2[tid]  = gb2[tid];
        sW3[tid]  = gW3[tid];
        sw10[tid] = gW1[tid * DIN];
        sb1[tid]  = gb1[tid];
    }
    for (int i = tid; i < H * C; i += blockDim.x) {
        int j = i / C, c = i % C;
        sW1c[i] = gW1[j * DIN + 1 + c];
    }
    __syncthreads();

    const int idx = blockIdx.x * blockDim.x + tid;
    if (idx >= B) return;

    float z = T[idx];

    // cond row: 8 floats, 16B-aligned (idx*32 bytes)
    const float4* cptr = reinterpret_cast<const float4*>(cond) + idx * 2;
    float4 c0 = cptr[0];
    float4 c1 = cptr[1];
    float cc[C] = {c0.x, c0.y, c0.z, c0.w, c1.x, c1.y, c1.z, c1.w};

    // Hoisted layer-1 preactivation (cond part + bias), fixed for all 80 evals.
    float pre1[H];
#pragma unroll
    for (int j = 0; j < H; j++) {
        float s = sb1[j];
#pragma unroll
        for (int c = 0; c < C; c++) s = fmaf(cc[c], sW1c[j * C + c], s);
        pre1[j] = s;
    }

    const float b3v = gb3[0];
    const float dt = 1.0f / (float)NSTEPS;     // (T1 - T0)/N_STEPS
    const float dt6 = dt / 6.0f;
    float logp = 0.0f;

#pragma unroll 1
    for (int step = 0; step < NSTEPS; step++) {
        float zs = z;      // stage input
        float az = 0.0f;   // sum coef*kz
        float ad = 0.0f;   // sum coef*kd

#pragma unroll 1
        for (int st = 0; st < 4; st++) {
            // ---- eval: (kz, kd) = f(zs) ----
            unsigned long long h1p[H / 2];
            unsigned long long d1p[H / 2];
#pragma unroll
            for (int p = 0; p < H / 2; p++) {
                float w0 = sw10[2 * p];
                float w1 = sw10[2 * p + 1];
                float x0 = fmaf(zs, w0, pre1[2 * p]);
                float x1 = fmaf(zs, w1, pre1[2 * p + 1]);
                float h0 = tanh_fast(x0);
                float h1 = tanh_fast(x1);
                float g0 = fmaf(-h0, h0, 1.0f) * w0;
                float g1 = fmaf(-h1, h1, 1.0f) * w1;
                h1p[p] = pack2(h0, h1);
                d1p[p] = pack2(g0, g1);
            }

            float dz = 0.0f, dv = 0.0f;
#pragma unroll 8
            for (int j = 0; j < H; j++) {
                unsigned long long sacc = 0ull;  // {0.f, 0.f}
                unsigned long long tacc = 0ull;
                const ulonglong2* wrow =
                    reinterpret_cast<const ulonglong2*>(sW2 + j * H);
#pragma unroll
                for (int i2 = 0; i2 < H / 4; i2++) {
                    ulonglong2 w = wrow[i2];
                    fma2(sacc, w.x, h1p[2 * i2]);
                    fma2(tacc, w.x, d1p[2 * i2]);
                    fma2(sacc, w.y, h1p[2 * i2 + 1]);
                    fma2(tacc, w.y, d1p[2 * i2 + 1]);
                }
                float s0, s1, t0, t1;
                unpack2(sacc, s0, s1);
                unpack2(tacc, t0, t1);
                float s  = (s0 + s1) + sb2[j];
                float h2 = tanh_fast(s);
                float g2 = fmaf(-h2, h2, 1.0f);
                float w3 = sW3[j];
                dz = fmaf(w3, h2, dz);
                dv = fmaf(w3, g2 * (t0 + t1), dv);
            }
            float kz = dz + b3v;
            float kd = dv;
            // ---- RK4 accumulate ----
            float coef = (st == 1 || st == 2) ? 2.0f : 1.0f;
            az = fmaf(coef, kz, az);
            ad = fmaf(coef, kd, ad);
            float a = (st == 2) ? dt : (0.5f * dt);  // unused at st==3
            zs = fmaf(a, kz, z);
        }

        z    = fmaf(dt6, az, z);
        logp = fmaf(dt6, ad, logp);
    }

    out[idx]     = z;      // z_T
    out[B + idx] = logp;   // delta_logp
}

extern "C" void kernel_launch(void* const* d_in, const int* in_sizes, int n_in,
                              void* d_out, int out_size) {
    const float* T    = (const float*)d_in[0];
    const float* cond = (const float*)d_in[1];
    const float* W1   = (const float*)d_in[2];
    const float* b1   = (const float*)d_in[3];
    const float* W2   = (const float*)d_in[4];
    const float* b2   = (const float*)d_in[5];
    const float* W3   = (const float*)d_in[6];
    const float* b3   = (const float*)d_in[7];
    float* out = (float*)d_out;

    const int B = in_sizes[0];                 // 524288 (T is [B,1])
    const int threads = 128;
    const int blocks = (B + threads - 1) / threads;
    cnf_kernel<<<blocks, threads>>>(T, cond, W1, b1, W2, b2, W3, b3, out, B);
}

// round 6
// speedup vs baseline: 1.2958x; 1.2958x over previous
#include <cuda_runtime.h>
#include <cuda_bf16.h>

// ConditionalCNF: B=524288 samples, scalar z, cond dim 8, 3-layer tanh MLP H=32,
// RK4 N_STEPS=20, augmented with exact divergence. One thread per sample.
//
// R5 changes vs R3 baseline:
//  - tanh.approx.f32 (1 MUFU, zero fma-pipe overhead) instead of ex2+rcp chain.
//  - pre1 (cond-dependent layer-1 preactivation) lives in shared memory
//    ([pair][tid] ull layout, conflict-free) -> frees ~32 regs -> 4 CTAs/SM.
//  - layer 1 fully packed with f32x2 (fma2/mul2), g = w - h^2*w via fma2 with
//    precomputed -w pairs.
//  - sacc initialized from packed {b2[j], 0} (moves an FADD off the fma pipe).

static constexpr int H = 32;
static constexpr int C = 8;
static constexpr int DIN = 9;          // 1 + C
static constexpr int NSTEPS = 20;
static constexpr int BLK = 128;

__device__ __forceinline__ float tanh_approx(float x) {
    float y;
    asm("tanh.approx.f32 %0, %1;" : "=f"(y) : "f"(x));
    return y;
}

__device__ __forceinline__ void fma2(unsigned long long& d,
                                     unsigned long long a,
                                     unsigned long long b) {
    asm("fma.rn.f32x2 %0, %1, %2, %3;" : "=l"(d) : "l"(a), "l"(b), "l"(d));
}

__device__ __forceinline__ unsigned long long fma2o(unsigned long long a,
                                                    unsigned long long b,
                                                    unsigned long long c) {
    unsigned long long d;
    asm("fma.rn.f32x2 %0, %1, %2, %3;" : "=l"(d) : "l"(a), "l"(b), "l"(c));
    return d;
}

__device__ __forceinline__ unsigned long long mul2(unsigned long long a,
                                                   unsigned long long b) {
    unsigned long long d;
    asm("mul.rn.f32x2 %0, %1, %2;" : "=l"(d) : "l"(a), "l"(b));
    return d;
}

__device__ __forceinline__ unsigned long long pack2(float lo, float hi) {
    unsigned long long r;
    asm("mov.b64 %0, {%1, %2};" : "=l"(r) : "f"(lo), "f"(hi));
    return r;
}

__device__ __forceinline__ void unpack2(unsigned long long v, float& lo, float& hi) {
    asm("mov.b64 {%0, %1}, %2;" : "=f"(lo), "=f"(hi) : "l"(v));
}

__global__ void __launch_bounds__(BLK, 4)
cnf_kernel(const float* __restrict__ T,
           const float* __restrict__ cond,
           const float* __restrict__ gW1,
           const float* __restrict__ gb1,
           const float* __restrict__ gW2,
           const float* __restrict__ gb2,
           const float* __restrict__ gW3,
           const float* __restrict__ gb3,
           float* __restrict__ out,
           int B)
{
    __shared__ __align__(16) float sW2[H * H];               // row-major, pair-contig
    __shared__ __align__(16) unsigned long long sb2p[H];     // {b2[j], 0}
    __shared__ float sW3[H];
    __shared__ __align__(16) unsigned long long sw10p[H/2];  // {w10[2p], w10[2p+1]}
    __shared__ __align__(16) unsigned long long snw10p[H/2]; // negated
    __shared__ float sW1c[H * C];                            // W1[:,1:9] [j][c]
    __shared__ float sb1[H];
    // per-thread pre1, packed pairs, [pair][tid] layout (conflict-free LDS.64)
    __shared__ __align__(16) unsigned long long sPre[(H/2) * BLK];

    const int tid = threadIdx.x;
    for (int i = tid; i < H * H; i += BLK) sW2[i] = gW2[i];
    if (tid < H) {
        sb2p[tid] = pack2(gb2[tid], 0.0f);
        sW3[tid]  = gW3[tid];
        sb1[tid]  = gb1[tid];
    }
    if (tid < H / 2) {
        float w0 = gW1[(2 * tid) * DIN];
        float w1 = gW1[(2 * tid + 1) * DIN];
        sw10p[tid]  = pack2(w0, w1);
        snw10p[tid] = pack2(-w0, -w1);
    }
    for (int i = tid; i < H * C; i += BLK) {
        int j = i / C, c = i % C;
        sW1c[i] = gW1[j * DIN + 1 + c];
    }
    __syncthreads();

    const int idx = blockIdx.x * BLK + tid;
    if (idx >= B) return;

    float z = T[idx];

    const float4* cptr = reinterpret_cast<const float4*>(cond) + idx * 2;
    float4 c0 = cptr[0];
    float4 c1 = cptr[1];
    float cc[C] = {c0.x, c0.y, c0.z, c0.w, c1.x, c1.y, c1.z, c1.w};

    // Hoisted layer-1 preactivation (cond part + bias) -> shared, pair-packed.
#pragma unroll
    for (int p = 0; p < H / 2; p++) {
        float s0 = sb1[2 * p], s1 = sb1[2 * p + 1];
#pragma unroll
        for (int c = 0; c < C; c++) {
            s0 = fmaf(cc[c], sW1c[(2 * p) * C + c], s0);
            s1 = fmaf(cc[c], sW1c[(2 * p + 1) * C + c], s1);
        }
        sPre[p * BLK + tid] = pack2(s0, s1);
    }

    const float b3v = gb3[0];
    const float dt = 1.0f / (float)NSTEPS;
    const float dt6 = dt / 6.0f;
    float logp = 0.0f;

#pragma unroll 1
    for (int step = 0; step < NSTEPS; step++) {
        float zs = z;
        float az = 0.0f;
        float ad = 0.0f;

#pragma unroll 1
        for (int st = 0; st < 4; st++) {
            // ---- layer 1 (packed) ----
            unsigned long long zz = pack2(zs, zs);
            unsigned long long h1p[H / 2];
            unsigned long long d1p[H / 2];
#pragma unroll
            for (int p = 0; p < H / 2; p++) {
                unsigned long long w  = sw10p[p];
                unsigned long long x  = fma2o(zz, w, sPre[p * BLK + tid]);
                float x0, x1;
                unpack2(x, x0, x1);
                unsigned long long h  = pack2(tanh_approx(x0), tanh_approx(x1));
                unsigned long long hh = mul2(h, h);
                h1p[p] = h;
                d1p[p] = fma2o(hh, snw10p[p], w);   // (1-h^2)*w = w - h^2*w
            }

            // ---- layer 2 + output ----
            float dz = 0.0f, dv = 0.0f;
#pragma unroll 8
            for (int j = 0; j < H; j++) {
                unsigned long long sacc = sb2p[j];  // {b2[j], 0}
                unsigned long long tacc = 0ull;
                const ulonglong2* wrow =
                    reinterpret_cast<const ulonglong2*>(sW2 + j * H);
#pragma unroll
                for (int i2 = 0; i2 < H / 4; i2++) {
                    ulonglong2 w = wrow[i2];
                    fma2(sacc, w.x, h1p[2 * i2]);
                    fma2(tacc, w.x, d1p[2 * i2]);
                    fma2(sacc, w.y, h1p[2 * i2 + 1]);
                    fma2(tacc, w.y, d1p[2 * i2 + 1]);
                }
                float s0, s1, t0, t1;
                unpack2(sacc, s0, s1);
                unpack2(tacc, t0, t1);
                float h2 = tanh_approx(s0 + s1);
                float g2 = fmaf(-h2, h2, 1.0f);
                float w3 = sW3[j];
                dz = fmaf(w3, h2, dz);
                dv = fmaf(w3, g2 * (t0 + t1), dv);
            }
            float kz = dz + b3v;
            float kd = dv;
            float coef = (st == 1 || st == 2) ? 2.0f : 1.0f;
            az = fmaf(coef, kz, az);
            ad = fmaf(coef, kd, ad);
            float a = (st == 2) ? dt : (0.5f * dt);
            zs = fmaf(a, kz, z);
        }

        z    = fmaf(dt6, az, z);
        logp = fmaf(dt6, ad, logp);
    }

    out[idx]     = z;
    out[B + idx] = logp;
}

extern "C" void kernel_launch(void* const* d_in, const int* in_sizes, int n_in,
                              void* d_out, int out_size) {
    const float* T    = (const float*)d_in[0];
    const float* cond = (const float*)d_in[1];
    const float* W1   = (const float*)d_in[2];
    const float* b1   = (const float*)d_in[3];
    const float* W2   = (const float*)d_in[4];
    const float* b2   = (const float*)d_in[5];
    const float* W3   = (const float*)d_in[6];
    const float* b3   = (const float*)d_in[7];
    float* out = (float*)d_out;

    const int B = in_sizes[0];
    const int blocks = (B + BLK - 1) / BLK;
    cnf_kernel<<<blocks, BLK>>>(T, cond, W1, b1, W2, b2, W3, b3, out, B);
}

// round 8
// speedup vs baseline: 2.4795x; 1.9136x over previous
#include <cuda_runtime.h>
#include <cstdint>

// ConditionalCNF via warp-level mma.sync (m16n8k8, tf32, 2-term compensated).
//
// Layout: 1 warp = 32 samples, fragment-native end to end.
//   lane: q = lane>>2 (row group), c4 = lane&3 (col group)
//   thread owns sample rows {q, q+8, q+16, q+24} (rs = 0..3)
//   thread owns k-cols {c4 + 4j, j=0..7}  (kt = j>>1, e = j&1 -> k = c4+4e+8kt)
//   D frag cols per thread: {2c4, 2c4+1} + 8*nt
// Layer1 computes h1/d1 straight into A-fragment slots; W2 lives as
// pre-rounded tf32 B fragments in smem ([tile][lane] ull, conflict-free);
// epilogue (tanh, W3) applied on D fragments; dz/dv reduced with 2 bfly
// shuffles per row. RK4 state replicated across each lane quad.
// No __syncthreads in the main loop.

using u32 = unsigned int;
using ull = unsigned long long;

static constexpr int NSTEPS = 20;
static constexpr int BLK = 128;
static constexpr u32 TFM = 0xFFFFE000u;   // tf32 truncation mask

__device__ __forceinline__ float tanh_approx(float x) {
    float y; asm("tanh.approx.f32 %0, %1;" : "=f"(y) : "f"(x)); return y;
}
__device__ __forceinline__ ull pack2(float lo, float hi) {
    ull r; asm("mov.b64 %0, {%1, %2};" : "=l"(r) : "f"(lo), "f"(hi)); return r;
}
__device__ __forceinline__ void unpack2(ull v, float& lo, float& hi) {
    asm("mov.b64 {%0, %1}, %2;" : "=f"(lo), "=f"(hi) : "l"(v));
}
__device__ __forceinline__ void unpack2u(ull v, u32& lo, u32& hi) {
    asm("mov.b64 {%0, %1}, %2;" : "=r"(lo), "=r"(hi) : "l"(v));
}
__device__ __forceinline__ ull fma2o(ull a, ull b, ull c) {
    ull d; asm("fma.rn.f32x2 %0, %1, %2, %3;" : "=l"(d) : "l"(a), "l"(b), "l"(c));
    return d;
}
__device__ __forceinline__ ull mul2(ull a, ull b) {
    ull d; asm("mul.rn.f32x2 %0, %1, %2;" : "=l"(d) : "l"(a), "l"(b));
    return d;
}
__device__ __forceinline__ u32 tf32_rna(float x) {
    u32 r; asm("cvt.rna.tf32.f32 %0, %1;" : "=r"(r) : "f"(x)); return r;
}
__device__ __forceinline__ void mma_tf32(float& c0, float& c1, float& c2, float& c3,
                                         u32 a0, u32 a1, u32 a2, u32 a3,
                                         u32 b0, u32 b1) {
    asm volatile("mma.sync.aligned.m16n8k8.row.col.f32.tf32.tf32.f32 "
                 "{%0,%1,%2,%3}, {%4,%5,%6,%7}, {%8,%9}, {%0,%1,%2,%3};"
                 : "+f"(c0), "+f"(c1), "+f"(c2), "+f"(c3)
                 : "r"(a0), "r"(a1), "r"(a2), "r"(a3), "r"(b0), "r"(b1));
}

__global__ void __launch_bounds__(BLK, 4)
cnf_kernel(const float* __restrict__ T,
           const float* __restrict__ cond,
           const float* __restrict__ gW1,
           const float* __restrict__ gb1,
           const float* __restrict__ gW2,
           const float* __restrict__ gb2,
           const float* __restrict__ gW3,
           const float* __restrict__ gb3,
           float* __restrict__ out,
           int B)
{
    // per-thread stashes, [slot][tid] lane-indexed (conflict-free LDS.64)
    __shared__ ull spre1[16 * BLK];   // layer1 preact pairs  (16 KB)
    __shared__ ull sd1  [16 * BLK];   // d1 pairs             (16 KB)
    __shared__ ull sB   [16 * 32];    // W2 tf32 B-frags [tile][lane] (4 KB)
    __shared__ ull sw10p[16];         // {w10[k0], w10[k1]} per (kt,c4)
    __shared__ ull snw10p[16];
    __shared__ ull sb2p [16];         // {b2[n0], b2[n0+1]} per (nt,c4)
    __shared__ ull sw3p [16];

    const int tid = threadIdx.x;
    const int ln  = tid & 31;
    const int wid = tid >> 5;
    const int q   = ln >> 2;
    const int c4  = ln & 3;

    // ---- one-time smem init ----
    // B fragments: tile t = kt*4+nt; per lane: n = q+8nt, k0 = c4+8kt, k1 = k0+4.
    for (int e = tid; e < 16 * 32; e += BLK) {
        int t = e >> 5, l = e & 31;
        int kt = t >> 2, nt = t & 3;
        int n  = (l >> 2) + 8 * nt;
        int k0 = (l & 3) + 8 * kt;
        u32 b0 = tf32_rna(gW2[n * 32 + k0]);
        u32 b1 = tf32_rna(gW2[n * 32 + k0 + 4]);
        sB[e] = ((ull)b1 << 32) | b0;
    }
    if (tid < 16) {
        int kt = tid >> 2, cc = tid & 3;
        float w0 = gW1[(cc + 8 * kt) * 9];
        float w1 = gW1[(cc + 4 + 8 * kt) * 9];
        sw10p[tid]  = pack2(w0, w1);
        snw10p[tid] = pack2(-w0, -w1);
        int nt = tid >> 2;
        int n0 = 2 * cc + 8 * nt;
        sb2p[tid] = pack2(gb2[n0], gb2[n0 + 1]);
        sw3p[tid] = pack2(gW3[n0], gW3[n0 + 1]);
    }

    // ---- per-thread setup: RK state + pre1 into smem ----
    const int gwbase = blockIdx.x * BLK + wid * 32;   // warp's first sample
    float z[4], logp[4];
#pragma unroll
    for (int rs = 0; rs < 4; rs++) {
        int s = gwbase + q + 8 * rs;
        z[rs] = __ldg(T + s);
        logp[rs] = 0.0f;
        // cond row
        const float4* cp = reinterpret_cast<const float4*>(cond) + s * 2;
        float4 ca = __ldg(cp), cb = __ldg(cp + 1);
        float cc[8] = {ca.x, ca.y, ca.z, ca.w, cb.x, cb.y, cb.z, cb.w};
#pragma unroll
        for (int kt = 0; kt < 4; kt++) {
            int k0 = c4 + 8 * kt, k1 = k0 + 4;
            float p0 = __ldg(gb1 + k0), p1 = __ldg(gb1 + k1);
#pragma unroll
            for (int c = 0; c < 8; c++) {
                p0 = fmaf(cc[c], __ldg(gW1 + k0 * 9 + 1 + c), p0);
                p1 = fmaf(cc[c], __ldg(gW1 + k1 * 9 + 1 + c), p1);
            }
            spre1[(rs * 4 + kt) * BLK + tid] = pack2(p0, p1);
        }
    }
    const float b3v = __ldg(gb3);
    __syncthreads();   // publish sB / small tables (pre1/sd1 are thread-private slots)

    const float dt  = 1.0f / (float)NSTEPS;
    const float dt6 = dt / 6.0f;

#pragma unroll 1
    for (int step = 0; step < NSTEPS; step++) {
        float zs[4], az[4], ad4[4];
#pragma unroll
        for (int rs = 0; rs < 4; rs++) { zs[rs] = z[rs]; az[rs] = 0.0f; ad4[rs] = 0.0f; }

#pragma unroll 1
        for (int st = 0; st < 4; st++) {
            // ======== S = h1 @ W2^T  (+ b2), 2-term tf32 ========
            float acc[32];   // [mt][nt][c0..c3]
#pragma unroll
            for (int mt = 0; mt < 2; mt++)
#pragma unroll
                for (int nt = 0; nt < 4; nt++) {
                    float blo, bhi; unpack2(sb2p[nt * 4 + c4], blo, bhi);
                    int ba = (mt * 4 + nt) * 4;
                    acc[ba + 0] = blo; acc[ba + 1] = bhi;
                    acc[ba + 2] = blo; acc[ba + 3] = bhi;
                }

            ull zzp[4];
#pragma unroll
            for (int rs = 0; rs < 4; rs++) zzp[rs] = pack2(zs[rs], zs[rs]);

#pragma unroll
            for (int kt = 0; kt < 4; kt++) {
                ull wp  = sw10p[kt * 4 + c4];
                ull nwp = snw10p[kt * 4 + c4];
                u32 ahi[4][2], alo[4][2];
#pragma unroll
                for (int rs = 0; rs < 4; rs++) {
                    ull pr = spre1[(rs * 4 + kt) * BLK + tid];
                    ull xp = fma2o(zzp[rs], wp, pr);
                    float x0, x1; unpack2(xp, x0, x1);
                    float h0 = tanh_approx(x0);
                    float h1 = tanh_approx(x1);
                    ull hp = pack2(h0, h1);
                    ull hh = mul2(hp, hp);
                    sd1[(rs * 4 + kt) * BLK + tid] = fma2o(hh, nwp, wp); // (1-h^2)w10
                    u32 h0u = __float_as_uint(h0) & TFM;
                    u32 h1u = __float_as_uint(h1) & TFM;
                    ahi[rs][0] = h0u; ahi[rs][1] = h1u;
                    alo[rs][0] = __float_as_uint(h0 - __uint_as_float(h0u)) & TFM;
                    alo[rs][1] = __float_as_uint(h1 - __uint_as_float(h1u)) & TFM;
                }
                ull bu[4];
#pragma unroll
                for (int nt = 0; nt < 4; nt++) bu[nt] = sB[(kt * 4 + nt) * 32 + ln];
#pragma unroll
                for (int mt = 0; mt < 2; mt++)
#pragma unroll
                    for (int nt = 0; nt < 4; nt++) {
                        u32 b0, b1; unpack2u(bu[nt], b0, b1);
                        int ba = (mt * 4 + nt) * 4;
                        mma_tf32(acc[ba], acc[ba+1], acc[ba+2], acc[ba+3],
                                 ahi[2*mt][0], ahi[2*mt+1][0], ahi[2*mt][1], ahi[2*mt+1][1],
                                 b0, b1);
                        mma_tf32(acc[ba], acc[ba+1], acc[ba+2], acc[ba+3],
                                 alo[2*mt][0], alo[2*mt+1][0], alo[2*mt][1], alo[2*mt+1][1],
                                 b0, b1);
                    }
            }

            // ======== S epilogue: tanh, dz partials, gw = (1-h2^2)*w3 ========
            float dzp[4] = {0.f, 0.f, 0.f, 0.f};
            float dvp[4] = {0.f, 0.f, 0.f, 0.f};
            float gw[32];
#pragma unroll
            for (int mt = 0; mt < 2; mt++)
#pragma unroll
                for (int nt = 0; nt < 4; nt++) {
                    float wlo, whi; unpack2(sw3p[nt * 4 + c4], wlo, whi);
                    int ba = (mt * 4 + nt) * 4;
                    float h2;
                    h2 = tanh_approx(acc[ba + 0]);
                    dzp[2*mt]   = fmaf(wlo, h2, dzp[2*mt]);
                    gw[ba + 0]  = fmaf(-h2, h2, 1.0f) * wlo;
                    h2 = tanh_approx(acc[ba + 1]);
                    dzp[2*mt]   = fmaf(whi, h2, dzp[2*mt]);
                    gw[ba + 1]  = fmaf(-h2, h2, 1.0f) * whi;
                    h2 = tanh_approx(acc[ba + 2]);
                    dzp[2*mt+1] = fmaf(wlo, h2, dzp[2*mt+1]);
                    gw[ba + 2]  = fmaf(-h2, h2, 1.0f) * wlo;
                    h2 = tanh_approx(acc[ba + 3]);
                    dzp[2*mt+1] = fmaf(whi, h2, dzp[2*mt+1]);
                    gw[ba + 3]  = fmaf(-h2, h2, 1.0f) * whi;
                }

            // ======== Tm = d1 @ W2^T, 2-term tf32 (reuse acc regs) ========
#pragma unroll
            for (int i = 0; i < 32; i++) acc[i] = 0.0f;
#pragma unroll
            for (int kt = 0; kt < 4; kt++) {
                u32 ahi[4][2], alo[4][2];
#pragma unroll
                for (int rs = 0; rs < 4; rs++) {
                    ull dp = sd1[(rs * 4 + kt) * BLK + tid];
                    float d0, d1; unpack2(dp, d0, d1);
                    u32 d0u = __float_as_uint(d0) & TFM;
                    u32 d1u = __float_as_uint(d1) & TFM;
                    ahi[rs][0] = d0u; ahi[rs][1] = d1u;
                    alo[rs][0] = __float_as_uint(d0 - __uint_as_float(d0u)) & TFM;
                    alo[rs][1] = __float_as_uint(d1 - __uint_as_float(d1u)) & TFM;
                }
                ull bu[4];
#pragma unroll
                for (int nt = 0; nt < 4; nt++) bu[nt] = sB[(kt * 4 + nt) * 32 + ln];
#pragma unroll
                for (int mt = 0; mt < 2; mt++)
#pragma unroll
                    for (int nt = 0; nt < 4; nt++) {
                        u32 b0, b1; unpack2u(bu[nt], b0, b1);
                        int ba = (mt * 4 + nt) * 4;
                        mma_tf32(acc[ba], acc[ba+1], acc[ba+2], acc[ba+3],
                                 ahi[2*mt][0], ahi[2*mt+1][0], ahi[2*mt][1], ahi[2*mt+1][1],
                                 b0, b1);
                        mma_tf32(acc[ba], acc[ba+1], acc[ba+2], acc[ba+3],
                                 alo[2*mt][0], alo[2*mt+1][0], alo[2*mt][1], alo[2*mt+1][1],
                                 b0, b1);
                    }
            }

            // ======== T epilogue: dv partials ========
#pragma unroll
            for (int mt = 0; mt < 2; mt++)
#pragma unroll
                for (int nt = 0; nt < 4; nt++) {
                    int ba = (mt * 4 + nt) * 4;
                    dvp[2*mt]   = fmaf(gw[ba + 0], acc[ba + 0], dvp[2*mt]);
                    dvp[2*mt]   = fmaf(gw[ba + 1], acc[ba + 1], dvp[2*mt]);
                    dvp[2*mt+1] = fmaf(gw[ba + 2], acc[ba + 2], dvp[2*mt+1]);
                    dvp[2*mt+1] = fmaf(gw[ba + 3], acc[ba + 3], dvp[2*mt+1]);
                }

            // ======== quad reduction + RK accumulate ========
            const float coef = (st == 1 || st == 2) ? 2.0f : 1.0f;
            const float a = (st == 2) ? dt : (0.5f * dt);
#pragma unroll
            for (int rs = 0; rs < 4; rs++) {
                float dz = dzp[rs], dv = dvp[rs];
                dz += __shfl_xor_sync(0xffffffffu, dz, 1);
                dz += __shfl_xor_sync(0xffffffffu, dz, 2);
                dv += __shfl_xor_sync(0xffffffffu, dv, 1);
                dv += __shfl_xor_sync(0xffffffffu, dv, 2);
                float kz = dz + b3v;
                az[rs]  = fmaf(coef, kz, az[rs]);
                ad4[rs] = fmaf(coef, dv, ad4[rs]);
                zs[rs]  = fmaf(a, kz, z[rs]);
            }
        }

#pragma unroll
        for (int rs = 0; rs < 4; rs++) {
            z[rs]    = fmaf(dt6, az[rs],  z[rs]);
            logp[rs] = fmaf(dt6, ad4[rs], logp[rs]);
        }
    }

    // ---- output: one lane per quad writes its 4 samples ----
    if (c4 == 0) {
#pragma unroll
        for (int rs = 0; rs < 4; rs++) {
            int s = gwbase + q + 8 * rs;
            out[s]     = z[rs];
            out[B + s] = logp[rs];
        }
    }
}

extern "C" void kernel_launch(void* const* d_in, const int* in_sizes, int n_in,
                              void* d_out, int out_size) {
    const float* T    = (const float*)d_in[0];
    const float* cond = (const float*)d_in[1];
    const float* W1   = (const float*)d_in[2];
    const float* b1   = (const float*)d_in[3];
    const float* W2   = (const float*)d_in[4];
    const float* b2   = (const float*)d_in[5];
    const float* W3   = (const float*)d_in[6];
    const float* b3   = (const float*)d_in[7];
    float* out = (float*)d_out;

    const int B = in_sizes[0];
    const int blocks = (B + BLK - 1) / BLK;
    cnf_kernel<<<blocks, BLK>>>(T, cond, W1, b1, W2, b2, W3, b3, out, B);
}

// round 9
// speedup vs baseline: 3.8220x; 1.5414x over previous
#include <cuda_runtime.h>
#include <cstdint>

// ConditionalCNF via warp-level mma.sync (m16n8k8, tf32, single-pass).
//
// 1 warp = 32 samples, fragment-native end to end.
//   lane: q = lane>>2, c4 = lane&3
//   thread rows {q+8rs, rs=0..3}; k-cols {c4+4e+8kt}
//   D cols per thread: {2c4, 2c4+1} + 8nt
// Per eval: layer1 (tanh.approx, packed f32x2) produces h1/d1 A-fragments in
// registers; ONE kt loop issues both matvecs (S = h1@W2^T, T = d1@W2^T) into
// dual accumulators (16 independent MMA chains); merged epilogue computes
// dz/dv per cell; 2 bfly shuffles reduce each row quad. No smem stash for d1,
// no tf32 compensation (rel_err budget: ~2e-4 vs 1e-3 gate).

using u32 = unsigned int;
using ull = unsigned long long;

static constexpr int NSTEPS = 20;
static constexpr int BLK = 128;

__device__ __forceinline__ float tanh_approx(float x) {
    float y; asm("tanh.approx.f32 %0, %1;" : "=f"(y) : "f"(x)); return y;
}
__device__ __forceinline__ ull pack2(float lo, float hi) {
    ull r; asm("mov.b64 %0, {%1, %2};" : "=l"(r) : "f"(lo), "f"(hi)); return r;
}
__device__ __forceinline__ void unpack2(ull v, float& lo, float& hi) {
    asm("mov.b64 {%0, %1}, %2;" : "=f"(lo), "=f"(hi) : "l"(v));
}
__device__ __forceinline__ void unpack2u(ull v, u32& lo, u32& hi) {
    asm("mov.b64 {%0, %1}, %2;" : "=r"(lo), "=r"(hi) : "l"(v));
}
__device__ __forceinline__ ull fma2o(ull a, ull b, ull c) {
    ull d; asm("fma.rn.f32x2 %0, %1, %2, %3;" : "=l"(d) : "l"(a), "l"(b), "l"(c));
    return d;
}
__device__ __forceinline__ ull mul2(ull a, ull b) {
    ull d; asm("mul.rn.f32x2 %0, %1, %2;" : "=l"(d) : "l"(a), "l"(b));
    return d;
}
__device__ __forceinline__ u32 tf32_rna(float x) {
    u32 r; asm("cvt.rna.tf32.f32 %0, %1;" : "=r"(r) : "f"(x)); return r;
}
__device__ __forceinline__ void mma_tf32(float& c0, float& c1, float& c2, float& c3,
                                         u32 a0, u32 a1, u32 a2, u32 a3,
                                         u32 b0, u32 b1) {
    asm volatile("mma.sync.aligned.m16n8k8.row.col.f32.tf32.tf32.f32 "
                 "{%0,%1,%2,%3}, {%4,%5,%6,%7}, {%8,%9}, {%0,%1,%2,%3};"
                 : "+f"(c0), "+f"(c1), "+f"(c2), "+f"(c3)
                 : "r"(a0), "r"(a1), "r"(a2), "r"(a3), "r"(b0), "r"(b1));
}

__global__ void __launch_bounds__(BLK, 4)
cnf_kernel(const float* __restrict__ T,
           const float* __restrict__ cond,
           const float* __restrict__ gW1,
           const float* __restrict__ gb1,
           const float* __restrict__ gW2,
           const float* __restrict__ gb2,
           const float* __restrict__ gW3,
           const float* __restrict__ gb3,
           float* __restrict__ out,
           int B)
{
    __shared__ ull spre1[16 * BLK];   // layer1 preact pairs [slot][tid] (16 KB)
    __shared__ ull sB   [16 * 32];    // W2 tf32 B-frags [tile][lane]     (4 KB)
    __shared__ ull sw10p[16];         // {w10[k0], w10[k1]} per (kt,c4)
    __shared__ ull snw10p[16];
    __shared__ ull sb2p [16];         // {b2[n0], b2[n0+1]} per (nt,c4)
    __shared__ ull sw3p [16];

    const int tid = threadIdx.x;
    const int ln  = tid & 31;
    const int wid = tid >> 5;
    const int q   = ln >> 2;
    const int c4  = ln & 3;

    // ---- one-time smem init ----
    for (int e = tid; e < 16 * 32; e += BLK) {
        int t = e >> 5, l = e & 31;
        int kt = t >> 2, nt = t & 3;
        int n  = (l >> 2) + 8 * nt;
        int k0 = (l & 3) + 8 * kt;
        u32 b0 = tf32_rna(gW2[n * 32 + k0]);
        u32 b1 = tf32_rna(gW2[n * 32 + k0 + 4]);
        sB[e] = ((ull)b1 << 32) | b0;
    }
    if (tid < 16) {
        int kt = tid >> 2, cc = tid & 3;
        float w0 = gW1[(cc + 8 * kt) * 9];
        float w1 = gW1[(cc + 4 + 8 * kt) * 9];
        sw10p[tid]  = pack2(w0, w1);
        snw10p[tid] = pack2(-w0, -w1);
        int nt = tid >> 2;
        int n0 = 2 * cc + 8 * nt;
        sb2p[tid] = pack2(gb2[n0], gb2[n0 + 1]);
        sw3p[tid] = pack2(gW3[n0], gW3[n0 + 1]);
    }

    // ---- per-thread setup: RK state + pre1 into smem ----
    const int gwbase = blockIdx.x * BLK + wid * 32;
    float z[4], logp[4];
#pragma unroll
    for (int rs = 0; rs < 4; rs++) {
        int s = gwbase + q + 8 * rs;
        z[rs] = __ldg(T + s);
        logp[rs] = 0.0f;
        const float4* cp = reinterpret_cast<const float4*>(cond) + s * 2;
        float4 ca = __ldg(cp), cb = __ldg(cp + 1);
        float cc[8] = {ca.x, ca.y, ca.z, ca.w, cb.x, cb.y, cb.z, cb.w};
#pragma unroll
        for (int kt = 0; kt < 4; kt++) {
            int k0 = c4 + 8 * kt, k1 = k0 + 4;
            float p0 = __ldg(gb1 + k0), p1 = __ldg(gb1 + k1);
#pragma unroll
            for (int c = 0; c < 8; c++) {
                p0 = fmaf(cc[c], __ldg(gW1 + k0 * 9 + 1 + c), p0);
                p1 = fmaf(cc[c], __ldg(gW1 + k1 * 9 + 1 + c), p1);
            }
            spre1[(rs * 4 + kt) * BLK + tid] = pack2(p0, p1);
        }
    }
    const float b3v = __ldg(gb3);
    __syncthreads();

    const float dt  = 1.0f / (float)NSTEPS;
    const float dt6 = dt / 6.0f;

#pragma unroll 1
    for (int step = 0; step < NSTEPS; step++) {
        float zs[4], az[4], ad4[4];
#pragma unroll
        for (int rs = 0; rs < 4; rs++) { zs[rs] = z[rs]; az[rs] = 0.0f; ad4[rs] = 0.0f; }

#pragma unroll 1
        for (int st = 0; st < 4; st++) {
            float accS[32], accT[32];
#pragma unroll
            for (int i = 0; i < 32; i++) { accS[i] = 0.0f; accT[i] = 0.0f; }

            ull zzp[4];
#pragma unroll
            for (int rs = 0; rs < 4; rs++) zzp[rs] = pack2(zs[rs], zs[rs]);

            // ---- fused layer1 + dual matvec over kt ----
#pragma unroll
            for (int kt = 0; kt < 4; kt++) {
                ull wp  = sw10p[kt * 4 + c4];
                ull nwp = snw10p[kt * 4 + c4];
                u32 ah[4][2], adf[4][2];
#pragma unroll
                for (int rs = 0; rs < 4; rs++) {
                    ull xp = fma2o(zzp[rs], wp, spre1[(rs * 4 + kt) * BLK + tid]);
                    float x0, x1; unpack2(xp, x0, x1);
                    float h0 = tanh_approx(x0);
                    float h1 = tanh_approx(x1);
                    ull hp = pack2(h0, h1);
                    ull hh = mul2(hp, hp);
                    ull dp = fma2o(hh, nwp, wp);        // (1-h^2)*w10
                    ah[rs][0] = __float_as_uint(h0);
                    ah[rs][1] = __float_as_uint(h1);
                    unpack2u(dp, adf[rs][0], adf[rs][1]);
                }
                ull bu[4];
#pragma unroll
                for (int nt = 0; nt < 4; nt++) bu[nt] = sB[(kt * 4 + nt) * 32 + ln];
#pragma unroll
                for (int mt = 0; mt < 2; mt++)
#pragma unroll
                    for (int nt = 0; nt < 4; nt++) {
                        u32 b0, b1; unpack2u(bu[nt], b0, b1);
                        int ba = (mt * 4 + nt) * 4;
                        mma_tf32(accS[ba], accS[ba+1], accS[ba+2], accS[ba+3],
                                 ah[2*mt][0], ah[2*mt+1][0], ah[2*mt][1], ah[2*mt+1][1],
                                 b0, b1);
                        mma_tf32(accT[ba], accT[ba+1], accT[ba+2], accT[ba+3],
                                 adf[2*mt][0], adf[2*mt+1][0], adf[2*mt][1], adf[2*mt+1][1],
                                 b0, b1);
                    }
            }

            // ---- merged epilogue: dz, dv per cell ----
            float dzp[4] = {0.f, 0.f, 0.f, 0.f};
            float dvp[4] = {0.f, 0.f, 0.f, 0.f};
#pragma unroll
            for (int mt = 0; mt < 2; mt++)
#pragma unroll
                for (int nt = 0; nt < 4; nt++) {
                    float blo, bhi; unpack2(sb2p[nt * 4 + c4], blo, bhi);
                    float wlo, whi; unpack2(sw3p[nt * 4 + c4], wlo, whi);
                    int ba = (mt * 4 + nt) * 4;
                    float h2, g;
                    h2 = tanh_approx(accS[ba + 0] + blo);
                    dzp[2*mt]   = fmaf(wlo, h2, dzp[2*mt]);
                    g = fmaf(-h2, h2, 1.0f) * wlo;
                    dvp[2*mt]   = fmaf(g, accT[ba + 0], dvp[2*mt]);
                    h2 = tanh_approx(accS[ba + 1] + bhi);
                    dzp[2*mt]   = fmaf(whi, h2, dzp[2*mt]);
                    g = fmaf(-h2, h2, 1.0f) * whi;
                    dvp[2*mt]   = fmaf(g, accT[ba + 1], dvp[2*mt]);
                    h2 = tanh_approx(accS[ba + 2] + blo);
                    dzp[2*mt+1] = fmaf(wlo, h2, dzp[2*mt+1]);
                    g = fmaf(-h2, h2, 1.0f) * wlo;
                    dvp[2*mt+1] = fmaf(g, accT[ba + 2], dvp[2*mt+1]);
                    h2 = tanh_approx(accS[ba + 3] + bhi);
                    dzp[2*mt+1] = fmaf(whi, h2, dzp[2*mt+1]);
                    g = fmaf(-h2, h2, 1.0f) * whi;
                    dvp[2*mt+1] = fmaf(g, accT[ba + 3], dvp[2*mt+1]);
                }

            // ---- quad reduction + RK accumulate ----
            const float coef = (st == 1 || st == 2) ? 2.0f : 1.0f;
            const float a = (st == 2) ? dt : (0.5f * dt);
#pragma unroll
            for (int rs = 0; rs < 4; rs++) {
                float dz = dzp[rs], dv = dvp[rs];
                dz += __shfl_xor_sync(0xffffffffu, dz, 1);
                dz += __shfl_xor_sync(0xffffffffu, dz, 2);
                dv += __shfl_xor_sync(0xffffffffu, dv, 1);
                dv += __shfl_xor_sync(0xffffffffu, dv, 2);
                float kz = dz + b3v;
                az[rs]  = fmaf(coef, kz, az[rs]);
                ad4[rs] = fmaf(coef, dv, ad4[rs]);
                zs[rs]  = fmaf(a, kz, z[rs]);
            }
        }

#pragma unroll
        for (int rs = 0; rs < 4; rs++) {
            z[rs]    = fmaf(dt6, az[rs],  z[rs]);
            logp[rs] = fmaf(dt6, ad4[rs], logp[rs]);
        }
    }

    if (c4 == 0) {
#pragma unroll
        for (int rs = 0; rs < 4; rs++) {
            int s = gwbase + q + 8 * rs;
            out[s]     = z[rs];
            out[B + s] = logp[rs];
        }
    }
}

extern "C" void kernel_launch(void* const* d_in, const int* in_sizes, int n_in,
                              void* d_out, int out_size) {
    const float* T    = (const float*)d_in[0];
    const float* cond = (const float*)d_in[1];
    const float* W1   = (const float*)d_in[2];
    const float* b1   = (const float*)d_in[3];
    const float* W2   = (const float*)d_in[4];
    const float* b2   = (const float*)d_in[5];
    const float* W3   = (const float*)d_in[6];
    const float* b3   = (const float*)d_in[7];
    float* out = (float*)d_out;

    const int B = in_sizes[0];
    const int blocks = (B + BLK - 1) / BLK;
    cnf_kernel<<<blocks, BLK>>>(T, cond, W1, b1, W2, b2, W3, b3, out, B);
}